// round 1
// baseline (speedup 1.0000x reference)
#include <cuda_runtime.h>

#define NODES 100000
#define RELS  3
#define NEDGE 320000
#define HIDF  128
#define NH    4
#define DH    32
#define HDF   128

// ---------------- scratch (device globals; no runtime allocation) ----------------
__device__ float g_Acomb[RELS][HIDF*HDF];          // Wt_src[r] @ Wg[r]
__device__ float g_cs[RELS][HDF];                   // bt_src[r] @ Wg[r]
__device__ float g_g[RELS][HIDF*NH];                // Wg[r] contracted with attn_r
__device__ float g_v[RELS][HIDF*NH];                // Wt_dst @ g  (er projection)
__device__ float g_erb[RELS][NH];                   // bt_dst @ g
__device__ float g_hs[RELS][(size_t)NODES*HDF];     // 153.6 MB
__device__ float g_el[RELS][NODES*NH];
__device__ float g_er[RELS][NODES*NH];
__device__ int   g_m[RELS][NODES*NH];               // ordered-int max
__device__ float g_ssum[RELS][NODES*NH];
__device__ float g_ex[RELS][NEDGE*NH];              // e then exp(e-m)
__device__ float g_rst[(size_t)NODES*RELS*HDF];     // [n][r][c], 153.6 MB
__device__ float g_wacc[RELS];
__device__ float g_aw[RELS];

// ---------------- helpers ----------------
__device__ __forceinline__ int ordf(float f) {
    int b = __float_as_int(f);
    return b >= 0 ? b : b ^ 0x7FFFFFFF;
}
__device__ __forceinline__ float unordf(int i) {
    return __int_as_float(i >= 0 ? i : i ^ 0x7FFFFFFF);
}
__device__ __forceinline__ float elu1(float x) {
    return x > 0.f ? x : expm1f(x);
}
__device__ __forceinline__ float fast_tanh(float x) {
    float y;
    asm("tanh.approx.f32 %0, %1;" : "=f"(y) : "f"(x));
    return y;
}

// ---------------- K0a: combined weights A_r, c_s, g ----------------
__global__ void k_prep1(const float* __restrict__ Wt_src, const float* __restrict__ bt_src,
                        const float* __restrict__ Wg, const float* __restrict__ attn_r)
{
    const int r = blockIdx.y;
    const int fBase = blockIdx.x * 16;
    const float* Ws  = Wt_src + (size_t)r*HIDF*HIDF;
    const float* Wgr = Wg + (size_t)r*HIDF*HDF;
    const int j = threadIdx.x & 127;
    const int frel = threadIdx.x >> 7;
    #pragma unroll
    for (int i = 0; i < 8; i++) {
        int f = fBase + frel*8 + i;
        float s = 0.f;
        for (int k = 0; k < HIDF; k++)
            s = fmaf(__ldg(Ws + f*HIDF + k), __ldg(Wgr + k*HDF + j), s);
        g_Acomb[r][f*HDF + j] = s;
    }
    if (blockIdx.x == 0) {
        if (threadIdx.x < 128) {
            float s = 0.f;
            for (int k = 0; k < HIDF; k++)
                s = fmaf(__ldg(bt_src + r*HIDF + k), __ldg(Wgr + k*HDF + j), s);
            g_cs[r][j] = s;
        } else {
            int k = threadIdx.x - 128;
            #pragma unroll
            for (int h = 0; h < NH; h++) {
                float s = 0.f;
                for (int d = 0; d < DH; d++)
                    s = fmaf(__ldg(Wgr + k*HDF + h*DH + d), __ldg(attn_r + (r*NH+h)*DH + d), s);
                g_g[r][k*NH + h] = s;
            }
        }
    }
}

// ---------------- K0b: v_r = Wt_dst @ g_r, er bias ----------------
__global__ void k_prep2(const float* __restrict__ Wt_dst, const float* __restrict__ bt_dst)
{
    const int r = blockIdx.x;
    const int tid = threadIdx.x;
    for (int o = tid; o < HIDF*NH; o += 256) {
        int f = o >> 2, h = o & 3;
        float s = 0.f;
        for (int k = 0; k < HIDF; k++)
            s = fmaf(__ldg(Wt_dst + f*HIDF + k), g_g[r][k*NH + h], s);
        g_v[r][o] = s;
    }
    if (tid < NH) {
        float s = 0.f;
        for (int k = 0; k < HIDF; k++)
            s = fmaf(__ldg(bt_dst + k), g_g[r][k*NH + tid], s);
        g_erb[r][tid] = s;
    }
}

// ---------------- K0c: zero/init accumulators ----------------
__global__ void k_init()
{
    const size_t i = (size_t)blockIdx.x*256 + threadIdx.x;
    const size_t rst4 = (size_t)NODES*RELS*HDF/4;      // 9.6M
    const size_t nh4  = (size_t)RELS*NODES*NH/4;       // 300K
    float4 z4 = make_float4(0.f,0.f,0.f,0.f);
    if (i < rst4) ((float4*)g_rst)[i] = z4;
    if (i < nh4) {
        ((float4*)g_ssum)[i] = z4;
        ((int4*)g_m)[i] = make_int4((int)0x80000000,(int)0x80000000,(int)0x80000000,(int)0x80000000);
    }
    if (i < RELS) g_wacc[i] = 0.f;
}

// ---------------- K1: hs = src_feats[r] @ Acomb[r] + c_s, fused el epilogue ----------------
__global__ void k_hs_gemm(const float* __restrict__ src_feats, const float* __restrict__ attn_l)
{
    const int r = blockIdx.z;
    const int rowBase = blockIdx.x * 128;
    __shared__ float As[32][132];
    __shared__ float Bs[32][132];
    __shared__ float el_s[128*NH];
    const int tid = threadIdx.x;
    const int tx = tid & 15, ty = tid >> 4;
    el_s[tid] = 0.f; el_s[tid + 256] = 0.f;
    float acc[8][8];
    #pragma unroll
    for (int i = 0; i < 8; i++)
        #pragma unroll
        for (int j = 0; j < 8; j++) acc[i][j] = 0.f;

    const float* A = src_feats + (size_t)r*NODES*HIDF;
    const float* B = g_Acomb[r];

    for (int kc = 0; kc < 4; kc++) {
        #pragma unroll
        for (int it = 0; it < 4; it++) {
            int t = tid + it*256;
            int row = t >> 3, c4 = t & 7;
            int grow = rowBase + row;
            float4 av = make_float4(0.f,0.f,0.f,0.f);
            if (grow < NODES)
                av = *(const float4*)(A + (size_t)grow*HIDF + kc*32 + c4*4);
            As[c4*4+0][row] = av.x; As[c4*4+1][row] = av.y;
            As[c4*4+2][row] = av.z; As[c4*4+3][row] = av.w;
        }
        #pragma unroll
        for (int it = 0; it < 4; it++) {
            int t = tid + it*256;
            int kk = t >> 5, j4 = t & 31;
            *(float4*)&Bs[kk][j4*4] = *(const float4*)(B + (size_t)(kc*32+kk)*HDF + j4*4);
        }
        __syncthreads();
        #pragma unroll
        for (int k = 0; k < 32; k++) {
            float a0[8], b0[8];
            *(float4*)&a0[0] = *(const float4*)&As[k][ty*8];
            *(float4*)&a0[4] = *(const float4*)&As[k][ty*8+4];
            *(float4*)&b0[0] = *(const float4*)&Bs[k][tx*8];
            *(float4*)&b0[4] = *(const float4*)&Bs[k][tx*8+4];
            #pragma unroll
            for (int i = 0; i < 8; i++)
                #pragma unroll
                for (int j = 0; j < 8; j++)
                    acc[i][j] = fmaf(a0[i], b0[j], acc[i][j]);
        }
        __syncthreads();
    }

    // epilogue: + bias, store hs, accumulate el = sum_d hs*attn_l
    const int h = tx >> 2;                       // cols tx*8..tx*8+7 sit in one head
    float alv[8], csv[8];
    #pragma unroll
    for (int j = 0; j < 8; j++) {
        alv[j] = __ldg(attn_l + r*HDF + tx*8 + j);
        csv[j] = g_cs[r][tx*8 + j];
    }
    float* HS = g_hs[r];
    #pragma unroll
    for (int i = 0; i < 8; i++) {
        int row = ty*8 + i, grow = rowBase + row;
        if (grow < NODES) {
            float vals[8]; float part = 0.f;
            #pragma unroll
            for (int j = 0; j < 8; j++) {
                float v = acc[i][j] + csv[j];
                vals[j] = v;
                part = fmaf(v, alv[j], part);
            }
            *(float4*)(HS + (size_t)grow*HDF + tx*8)     = make_float4(vals[0],vals[1],vals[2],vals[3]);
            *(float4*)(HS + (size_t)grow*HDF + tx*8 + 4) = make_float4(vals[4],vals[5],vals[6],vals[7]);
            atomicAdd(&el_s[row*NH + h], part);
        }
    }
    __syncthreads();
    if (tid < 128) {
        int grow = rowBase + tid;
        if (grow < NODES)
            *(float4*)(g_el[r] + (size_t)grow*NH) = *(float4*)&el_s[tid*NH];
    }
}

// ---------------- K2: er[n,h] = dst_feat[n] . v_r[:,h] + erb ----------------
__global__ void k_er(const float* __restrict__ dst_feat)
{
    __shared__ float vs[RELS*HIDF*NH];
    const int tid = threadIdx.x;
    for (int i = tid; i < RELS*HIDF*NH; i += 256)
        vs[i] = ((const float*)g_v)[i];
    __syncthreads();
    const int warp = tid >> 5, lane = tid & 31;
    const int n = blockIdx.x*8 + warp;
    if (n >= NODES) return;
    float x[4];
    #pragma unroll
    for (int q = 0; q < 4; q++) x[q] = dst_feat[(size_t)n*HIDF + lane + q*32];
    float p[RELS][NH];
    #pragma unroll
    for (int r = 0; r < RELS; r++)
        #pragma unroll
        for (int h = 0; h < NH; h++) p[r][h] = 0.f;
    #pragma unroll
    for (int q = 0; q < 4; q++) {
        int f = lane + q*32;
        #pragma unroll
        for (int r = 0; r < RELS; r++)
            #pragma unroll
            for (int h = 0; h < NH; h++)
                p[r][h] = fmaf(x[q], vs[(r*HIDF + f)*NH + h], p[r][h]);
    }
    #pragma unroll
    for (int off = 16; off; off >>= 1)
        #pragma unroll
        for (int r = 0; r < RELS; r++)
            #pragma unroll
            for (int h = 0; h < NH; h++)
                p[r][h] += __shfl_xor_sync(0xFFFFFFFFu, p[r][h], off);
    if (lane < RELS*NH) {
        int r = lane >> 2, h = lane & 3;
        g_er[r][(size_t)n*NH + h] = p[r][h] + g_erb[r][h];
    }
}

// ---------------- K3: e = lrelu(el[s]+er[d]); segment max ----------------
__global__ void k_edge1(const int* __restrict__ src_idx, const int* __restrict__ dst_idx)
{
    const int r = blockIdx.y;
    const int e = blockIdx.x*256 + threadIdx.x;
    if (e >= NEDGE) return;
    const int s = src_idx[(size_t)r*NEDGE + e];
    const int d = dst_idx[(size_t)r*NEDGE + e];
    float4 el4 = *(const float4*)(g_el[r] + (size_t)s*NH);
    float4 er4 = *(const float4*)(g_er[r] + (size_t)d*NH);
    float v[4] = {el4.x+er4.x, el4.y+er4.y, el4.z+er4.z, el4.w+er4.w};
    #pragma unroll
    for (int h = 0; h < NH; h++) {
        v[h] = v[h] > 0.f ? v[h] : 0.2f*v[h];
        atomicMax(&g_m[r][(size_t)d*NH + h], ordf(v[h]));
    }
    *(float4*)(g_ex[r] + (size_t)e*NH) = make_float4(v[0],v[1],v[2],v[3]);
}

// ---------------- K4: ex = exp(e - m[d]); segment sum ----------------
__global__ void k_edge2(const int* __restrict__ dst_idx)
{
    const int r = blockIdx.y;
    const int e = blockIdx.x*256 + threadIdx.x;
    if (e >= NEDGE) return;
    const int d = dst_idx[(size_t)r*NEDGE + e];
    float4 e4 = *(const float4*)(g_ex[r] + (size_t)e*NH);
    float v[4] = {e4.x, e4.y, e4.z, e4.w};
    #pragma unroll
    for (int h = 0; h < NH; h++) {
        float m = unordf(g_m[r][(size_t)d*NH + h]);
        float ex = __expf(v[h] - m);
        v[h] = ex;
        atomicAdd(&g_ssum[r][(size_t)d*NH + h], ex);
    }
    *(float4*)(g_ex[r] + (size_t)e*NH) = make_float4(v[0],v[1],v[2],v[3]);
}

// ---------------- K5: rst[d] += alpha * hs[s]  (warp per edge) ----------------
__global__ void k_edge3(const int* __restrict__ src_idx, const int* __restrict__ dst_idx)
{
    const int r = blockIdx.y;
    const int warp = threadIdx.x >> 5, lane = threadIdx.x & 31;
    const int e = blockIdx.x*8 + warp;
    if (e >= NEDGE) return;
    const int s = src_idx[(size_t)r*NEDGE + e];
    const int d = dst_idx[(size_t)r*NEDGE + e];
    const int h = lane >> 3;
    float ex = g_ex[r][(size_t)e*NH + h];
    float ss = g_ssum[r][(size_t)d*NH + h];
    float alpha = ex / (ss + 1e-9f);
    float4 hv = *(const float4*)(g_hs[r] + (size_t)s*HDF + lane*4);
    float* out = g_rst + ((size_t)d*RELS + r)*HDF + lane*4;
    atomicAdd(out+0, alpha*hv.x);
    atomicAdd(out+1, alpha*hv.y);
    atomicAdd(out+2, alpha*hv.z);
    atomicAdd(out+3, alpha*hv.w);
}

// ---------------- K6: w = tanh(elu(rst+bias_g)@W1 + b1) . W2, accumulate mean ----------------
__global__ void k_w_gemm(const float* __restrict__ bias_g, const float* __restrict__ W1,
                         const float* __restrict__ b1, const float* __restrict__ W2)
{
    __shared__ float As[32][132];
    __shared__ float Bs[32][132];
    __shared__ float row_w[128];
    const int tid = threadIdx.x;
    const int tx = tid & 15, ty = tid >> 4;
    const int rowBase = blockIdx.x * 128;       // rows over N*R ([n][r] order)
    if (tid < 128) row_w[tid] = 0.f;
    float acc[8][8];
    #pragma unroll
    for (int i = 0; i < 8; i++)
        #pragma unroll
        for (int j = 0; j < 8; j++) acc[i][j] = 0.f;

    for (int kc = 0; kc < 4; kc++) {
        #pragma unroll
        for (int it = 0; it < 4; it++) {
            int t = tid + it*256;
            int row = t >> 3, c4 = t & 7;
            int grow = rowBase + row;
            float4 av = make_float4(0.f,0.f,0.f,0.f);
            if (grow < NODES*RELS) {
                int rr = grow % RELS;
                av = *(const float4*)(g_rst + (size_t)grow*HDF + kc*32 + c4*4);
                float4 bg = *(const float4*)(bias_g + (size_t)rr*HDF + kc*32 + c4*4);
                av.x = elu1(av.x + bg.x); av.y = elu1(av.y + bg.y);
                av.z = elu1(av.z + bg.z); av.w = elu1(av.w + bg.w);
            }
            As[c4*4+0][row] = av.x; As[c4*4+1][row] = av.y;
            As[c4*4+2][row] = av.z; As[c4*4+3][row] = av.w;
        }
        #pragma unroll
        for (int it = 0; it < 4; it++) {
            int t = tid + it*256;
            int kk = t >> 5, j4 = t & 31;
            *(float4*)&Bs[kk][j4*4] = *(const float4*)(W1 + (size_t)(kc*32+kk)*HDF + j4*4);
        }
        __syncthreads();
        #pragma unroll
        for (int k = 0; k < 32; k++) {
            float a0[8], b0[8];
            *(float4*)&a0[0] = *(const float4*)&As[k][ty*8];
            *(float4*)&a0[4] = *(const float4*)&As[k][ty*8+4];
            *(float4*)&b0[0] = *(const float4*)&Bs[k][tx*8];
            *(float4*)&b0[4] = *(const float4*)&Bs[k][tx*8+4];
            #pragma unroll
            for (int i = 0; i < 8; i++)
                #pragma unroll
                for (int j = 0; j < 8; j++)
                    acc[i][j] = fmaf(a0[i], b0[j], acc[i][j]);
        }
        __syncthreads();
    }
    float b1v[8], w2v[8];
    #pragma unroll
    for (int j = 0; j < 8; j++) { b1v[j] = b1[tx*8+j]; w2v[j] = W2[tx*8+j]; }
    #pragma unroll
    for (int i = 0; i < 8; i++) {
        int row = ty*8 + i;
        if (rowBase + row < NODES*RELS) {
            float part = 0.f;
            #pragma unroll
            for (int j = 0; j < 8; j++)
                part = fmaf(fast_tanh(acc[i][j] + b1v[j]), w2v[j], part);
            atomicAdd(&row_w[row], part);
        }
    }
    __syncthreads();
    if (tid == 0) {
        float s0 = 0.f, s1 = 0.f, s2 = 0.f;
        int lim = NODES*RELS - rowBase; if (lim > 128) lim = 128;
        for (int i2 = 0; i2 < lim; i2++) {
            int rr = (rowBase + i2) % RELS;
            float v = row_w[i2];
            if (rr == 0) s0 += v; else if (rr == 1) s1 += v; else s2 += v;
        }
        atomicAdd(&g_wacc[0], s0);
        atomicAdd(&g_wacc[1], s1);
        atomicAdd(&g_wacc[2], s2);
    }
}

// ---------------- K7: softmax over relation means -> a[r]; write att_mp ----------------
__global__ void k_softmax(float* __restrict__ out, int out_size)
{
    if (threadIdx.x == 0) {
        float w[RELS], mx = -3.0e38f;
        #pragma unroll
        for (int r = 0; r < RELS; r++) { w[r] = g_wacc[r] / (float)NODES; mx = fmaxf(mx, w[r]); }
        float sum = 0.f;
        #pragma unroll
        for (int r = 0; r < RELS; r++) { w[r] = __expf(w[r] - mx); sum += w[r]; }
        #pragma unroll
        for (int r = 0; r < RELS; r++) {
            float a = w[r] / sum;
            g_aw[r] = a;
            if (out_size >= NODES*HDF + RELS)
                out[(size_t)NODES*HDF + r] = a;
        }
    }
}

// ---------------- K8: z = sum_r a[r] * elu(rst[n][r] + bias_g[r]) ----------------
__global__ void k_final(const float* __restrict__ bias_g, float* __restrict__ out)
{
    const size_t idx = (size_t)blockIdx.x*256 + threadIdx.x;  // over N*32 float4 slots
    if (idx >= (size_t)NODES*32) return;
    const int n = (int)(idx >> 5);
    const int c4 = ((int)idx & 31) * 4;
    float4 accv = make_float4(0.f,0.f,0.f,0.f);
    #pragma unroll
    for (int r = 0; r < RELS; r++) {
        float a = g_aw[r];
        float4 v = *(const float4*)(g_rst + ((size_t)n*RELS + r)*HDF + c4);
        float4 b = *(const float4*)(bias_g + (size_t)r*HDF + c4);
        accv.x = fmaf(a, elu1(v.x + b.x), accv.x);
        accv.y = fmaf(a, elu1(v.y + b.y), accv.y);
        accv.z = fmaf(a, elu1(v.z + b.z), accv.z);
        accv.w = fmaf(a, elu1(v.w + b.w), accv.w);
    }
    *(float4*)(out + (size_t)n*HDF + c4) = accv;
}

// ---------------- launch ----------------
extern "C" void kernel_launch(void* const* d_in, const int* in_sizes, int n_in,
                              void* d_out, int out_size)
{
    const float* dst_feat  = (const float*)d_in[0];
    const float* src_feats = (const float*)d_in[1];
    const int*   src_idx   = (const int*)  d_in[2];
    const int*   dst_idx   = (const int*)  d_in[3];
    const float* Wt_dst    = (const float*)d_in[4];
    const float* bt_dst    = (const float*)d_in[5];
    const float* Wt_src    = (const float*)d_in[6];
    const float* bt_src    = (const float*)d_in[7];
    const float* Wg        = (const float*)d_in[8];
    const float* attn_l    = (const float*)d_in[9];
    const float* attn_r    = (const float*)d_in[10];
    const float* bias_g    = (const float*)d_in[11];
    const float* W1        = (const float*)d_in[12];
    const float* b1        = (const float*)d_in[13];
    const float* W2        = (const float*)d_in[14];
    float* out = (float*)d_out;

    k_prep1<<<dim3(8, RELS), 256>>>(Wt_src, bt_src, Wg, attn_r);
    k_prep2<<<RELS, 256>>>(Wt_dst, bt_dst);
    k_init<<<37500, 256>>>();
    k_hs_gemm<<<dim3((NODES + 127)/128, 1, RELS), 256>>>(src_feats, attn_l);
    k_er<<<(NODES + 7)/8, 256>>>(dst_feat);
    k_edge1<<<dim3((NEDGE + 255)/256, RELS), 256>>>(src_idx, dst_idx);
    k_edge2<<<dim3((NEDGE + 255)/256, RELS), 256>>>(dst_idx);
    k_edge3<<<dim3((NEDGE + 7)/8, RELS), 256>>>(src_idx, dst_idx);
    k_w_gemm<<<(NODES*RELS + 127)/128, 256>>>(bias_g, W1, b1, W2);
    k_softmax<<<1, 32>>>(out, out_size);
    k_final<<<(NODES*32 + 255)/256, 256>>>(bias_g, out);
}

// round 2
// speedup vs baseline: 1.5302x; 1.5302x over previous
#include <cuda_runtime.h>

#define NODES 100000
#define RELS  3
#define NEDGE 320000
#define HIDF  128
#define NH    4
#define DH    32
#define HDF   128
#define NR    (NODES*RELS)

// ---------------- scratch (device globals; no runtime allocation) ----------------
__device__ __align__(16) float g_Acomb[RELS][HIDF*HDF];   // Wt_src[r] @ Wg[r]
__device__ __align__(16) float g_cs[RELS][HDF];           // bt_src[r] @ Wg[r]
__device__ __align__(16) float g_g[RELS][HIDF*NH];        // Wg[r] contracted with attn_r
__device__ __align__(16) float g_v[RELS][HIDF*NH];        // Wt_dst @ g (er projection)
__device__ __align__(16) float g_erb[RELS][NH];           // bt_dst @ g
__device__ __align__(16) float g_hs[RELS][(size_t)NODES*HDF];  // 153.6 MB
__device__ __align__(16) float g_el[RELS][NODES*NH];
__device__ __align__(16) float g_er[RELS][NODES*NH];
__device__ __align__(16) float g_ssum[RELS][NODES*NH];
__device__ __align__(16) float g_ex[RELS][NEDGE*NH];      // exp(e) per edge
__device__ __align__(16) float g_rst[(size_t)NODES*RELS*HDF];  // [n][r][c]
__device__ float g_wacc[RELS];
__device__ float g_aw[RELS];

// ---------------- helpers ----------------
__device__ __forceinline__ float elu1(float x) {
    return x > 0.f ? x : expm1f(x);
}
__device__ __forceinline__ float fast_tanh(float x) {
    float y;
    asm("tanh.approx.f32 %0, %1;" : "=f"(y) : "f"(x));
    return y;
}
__device__ __forceinline__ void red_v4(float* p, float a, float b, float c, float d) {
    asm volatile("red.global.add.v4.f32 [%0], {%1,%2,%3,%4};"
                 :: "l"(p), "f"(a), "f"(b), "f"(c), "f"(d) : "memory");
}

// ---------------- K0a: combined weights A_r, c_s, g ----------------
__global__ void k_prep1(const float* __restrict__ Wt_src, const float* __restrict__ bt_src,
                        const float* __restrict__ Wg, const float* __restrict__ attn_r)
{
    const int r = blockIdx.y;
    const int fBase = blockIdx.x * 16;
    const float* Ws  = Wt_src + (size_t)r*HIDF*HIDF;
    const float* Wgr = Wg + (size_t)r*HIDF*HDF;
    const int j = threadIdx.x & 127;
    const int frel = threadIdx.x >> 7;
    #pragma unroll
    for (int i = 0; i < 8; i++) {
        int f = fBase + frel*8 + i;
        float s = 0.f;
        for (int k = 0; k < HIDF; k++)
            s = fmaf(__ldg(Ws + f*HIDF + k), __ldg(Wgr + k*HDF + j), s);
        g_Acomb[r][f*HDF + j] = s;
    }
    if (blockIdx.x == 0) {
        if (threadIdx.x < 128) {
            float s = 0.f;
            for (int k = 0; k < HIDF; k++)
                s = fmaf(__ldg(bt_src + r*HIDF + k), __ldg(Wgr + k*HDF + j), s);
            g_cs[r][j] = s;
        } else {
            int k = threadIdx.x - 128;
            #pragma unroll
            for (int h = 0; h < NH; h++) {
                float s = 0.f;
                for (int d = 0; d < DH; d++)
                    s = fmaf(__ldg(Wgr + k*HDF + h*DH + d), __ldg(attn_r + (r*NH+h)*DH + d), s);
                g_g[r][k*NH + h] = s;
            }
        }
    }
}

// ---------------- K0b: v_r = Wt_dst @ g_r, er bias ----------------
__global__ void k_prep2(const float* __restrict__ Wt_dst, const float* __restrict__ bt_dst)
{
    const int r = blockIdx.x;
    const int tid = threadIdx.x;
    for (int o = tid; o < HIDF*NH; o += 256) {
        int f = o >> 2, h = o & 3;
        float s = 0.f;
        for (int k = 0; k < HIDF; k++)
            s = fmaf(__ldg(Wt_dst + f*HIDF + k), g_g[r][k*NH + h], s);
        g_v[r][o] = s;
    }
    if (tid < NH) {
        float s = 0.f;
        for (int k = 0; k < HIDF; k++)
            s = fmaf(__ldg(bt_dst + k), g_g[r][k*NH + tid], s);
        g_erb[r][tid] = s;
    }
}

// ---------------- K0c: zero accumulators ----------------
__global__ void k_init()
{
    const size_t i = (size_t)blockIdx.x*256 + threadIdx.x;
    const size_t rst4 = (size_t)NODES*RELS*HDF/4;      // 9.6M
    const size_t nh4  = (size_t)RELS*NODES*NH/4;       // 300K
    float4 z4 = make_float4(0.f,0.f,0.f,0.f);
    if (i < rst4) ((float4*)g_rst)[i] = z4;
    if (i < nh4)  ((float4*)g_ssum)[i] = z4;
    if (i < RELS) g_wacc[i] = 0.f;
}

// =====================================================================
// GEMM K1: hs = src_feats[r] @ Acomb[r] + c_s, fused el epilogue
// BM=128 BN=128 BK=16, 256 threads, 8x8 per thread, register double-buffer
// =====================================================================
__global__ __launch_bounds__(256, 2)
void k_hs_gemm(const float* __restrict__ src_feats, const float* __restrict__ attn_l)
{
    const int r = blockIdx.y;
    const int rowBase = blockIdx.x * 128;
    __shared__ float As[16][132];   // [k][row]
    __shared__ float Bs[16][132];   // [k][col]
    const int tid = threadIdx.x;
    const int tx = tid & 15, ty = tid >> 4;

    const float* A = src_feats + (size_t)r*NODES*HIDF;
    const float* B = g_Acomb[r];

    // prefetch addressing
    const int arow0 = (tid*2) >> 2;        // rows for it=0/1: f4 = tid+it*256
    const int ak40  = (tid*2) & 3;         // note: f4 = 2*tid + it  pattern below
    float4 ra[2], rb[2];

    // we use f4 = tid + it*256  (it=0,1)
    #pragma unroll
    for (int it = 0; it < 2; it++) {
        int f4 = tid + it*256;
        int arow = f4 >> 2, ak4 = f4 & 3;
        int grow = rowBase + arow; if (grow >= NODES) grow = NODES-1;
        ra[it] = *(const float4*)(A + (size_t)grow*HIDF + 0*16 + ak4*4);
        int bk = f4 >> 5, bj4 = f4 & 31;
        rb[it] = *(const float4*)(B + (size_t)(0*16 + bk)*HDF + bj4*4);
    }
    (void)arow0; (void)ak40;

    float acc[8][8];
    #pragma unroll
    for (int i = 0; i < 8; i++)
        #pragma unroll
        for (int j = 0; j < 8; j++) acc[i][j] = 0.f;

    #pragma unroll 1
    for (int kc = 0; kc < 8; kc++) {
        if (kc) __syncthreads();
        #pragma unroll
        for (int it = 0; it < 2; it++) {
            int f4 = tid + it*256;
            int arow = f4 >> 2, ak4 = f4 & 3;
            As[ak4*4+0][arow] = ra[it].x;
            As[ak4*4+1][arow] = ra[it].y;
            As[ak4*4+2][arow] = ra[it].z;
            As[ak4*4+3][arow] = ra[it].w;
            int bk = f4 >> 5, bj4 = f4 & 31;
            *(float4*)&Bs[bk][bj4*4] = rb[it];
        }
        __syncthreads();
        if (kc < 7) {
            #pragma unroll
            for (int it = 0; it < 2; it++) {
                int f4 = tid + it*256;
                int arow = f4 >> 2, ak4 = f4 & 3;
                int grow = rowBase + arow; if (grow >= NODES) grow = NODES-1;
                ra[it] = *(const float4*)(A + (size_t)grow*HIDF + (kc+1)*16 + ak4*4);
                int bk = f4 >> 5, bj4 = f4 & 31;
                rb[it] = *(const float4*)(B + (size_t)((kc+1)*16 + bk)*HDF + bj4*4);
            }
        }
        #pragma unroll
        for (int k = 0; k < 16; k++) {
            float a0[8], b0[8];
            *(float4*)&a0[0] = *(const float4*)&As[k][ty*8];
            *(float4*)&a0[4] = *(const float4*)&As[k][ty*8+4];
            *(float4*)&b0[0] = *(const float4*)&Bs[k][tx*8];
            *(float4*)&b0[4] = *(const float4*)&Bs[k][tx*8+4];
            #pragma unroll
            for (int i = 0; i < 8; i++)
                #pragma unroll
                for (int j = 0; j < 8; j++)
                    acc[i][j] = fmaf(a0[i], b0[j], acc[i][j]);
        }
    }

    // epilogue: + bias, store hs, el = sum over head cols via quad shuffle
    const int h = tx >> 2;
    float alv[8], csv[8];
    #pragma unroll
    for (int j = 0; j < 8; j++) {
        alv[j] = __ldg(attn_l + r*HDF + tx*8 + j);
        csv[j] = g_cs[r][tx*8 + j];
    }
    float* HS = g_hs[r];
    #pragma unroll
    for (int i = 0; i < 8; i++) {
        int grow = rowBase + ty*8 + i;
        float vals[8]; float part = 0.f;
        #pragma unroll
        for (int j = 0; j < 8; j++) {
            float v = acc[i][j] + csv[j];
            vals[j] = v;
            part = fmaf(v, alv[j], part);
        }
        // reduce over 4 tx lanes of this head (consecutive lanes)
        part += __shfl_xor_sync(0xFFFFFFFFu, part, 1);
        part += __shfl_xor_sync(0xFFFFFFFFu, part, 2);
        if (grow < NODES) {
            *(float4*)(HS + (size_t)grow*HDF + tx*8)     = make_float4(vals[0],vals[1],vals[2],vals[3]);
            *(float4*)(HS + (size_t)grow*HDF + tx*8 + 4) = make_float4(vals[4],vals[5],vals[6],vals[7]);
            if ((tx & 3) == 0)
                g_el[r][(size_t)grow*NH + h] = part;
        }
    }
}

// ---------------- K2: er[n,h] = dst_feat[n] . v_r[:,h] + erb ----------------
__global__ void k_er(const float* __restrict__ dst_feat)
{
    __shared__ float vs[RELS*HIDF*NH];
    const int tid = threadIdx.x;
    for (int i = tid; i < RELS*HIDF*NH; i += 256)
        vs[i] = ((const float*)g_v)[i];
    __syncthreads();
    const int warp = tid >> 5, lane = tid & 31;
    const int n = blockIdx.x*8 + warp;
    if (n >= NODES) return;
    float x[4];
    #pragma unroll
    for (int q = 0; q < 4; q++) x[q] = dst_feat[(size_t)n*HIDF + lane + q*32];
    float p[RELS][NH];
    #pragma unroll
    for (int r = 0; r < RELS; r++)
        #pragma unroll
        for (int h = 0; h < NH; h++) p[r][h] = 0.f;
    #pragma unroll
    for (int q = 0; q < 4; q++) {
        int f = lane + q*32;
        #pragma unroll
        for (int r = 0; r < RELS; r++)
            #pragma unroll
            for (int h = 0; h < NH; h++)
                p[r][h] = fmaf(x[q], vs[(r*HIDF + f)*NH + h], p[r][h]);
    }
    #pragma unroll
    for (int off = 16; off; off >>= 1)
        #pragma unroll
        for (int r = 0; r < RELS; r++)
            #pragma unroll
            for (int h = 0; h < NH; h++)
                p[r][h] += __shfl_xor_sync(0xFFFFFFFFu, p[r][h], off);
    if (lane < RELS*NH) {
        int r = lane >> 2, h = lane & 3;
        g_er[r][(size_t)n*NH + h] = p[r][h] + g_erb[r][h];
    }
}

// ---------------- K3: ex = exp(lrelu(el[s]+er[d])); ssum via v4 red ----------------
__global__ void k_edge_a(const int* __restrict__ src_idx, const int* __restrict__ dst_idx)
{
    const int r = blockIdx.y;
    const int e = blockIdx.x*256 + threadIdx.x;
    if (e >= NEDGE) return;
    const int s = src_idx[(size_t)r*NEDGE + e];
    const int d = dst_idx[(size_t)r*NEDGE + e];
    float4 el4 = *(const float4*)(g_el[r] + (size_t)s*NH);
    float4 er4 = *(const float4*)(g_er[r] + (size_t)d*NH);
    float v[4] = {el4.x+er4.x, el4.y+er4.y, el4.z+er4.z, el4.w+er4.w};
    #pragma unroll
    for (int h = 0; h < NH; h++) {
        float t = v[h] > 0.f ? v[h] : 0.2f*v[h];
        v[h] = __expf(t);
    }
    *(float4*)(g_ex[r] + (size_t)e*NH) = make_float4(v[0],v[1],v[2],v[3]);
    red_v4(&g_ssum[r][(size_t)d*NH], v[0], v[1], v[2], v[3]);
}

// ---------------- K4: rst[d] += alpha * hs[s]  (warp/edge, v4 red) ----------------
__global__ void k_edge_b(const int* __restrict__ src_idx, const int* __restrict__ dst_idx, int r)
{
    const int warp = threadIdx.x >> 5, lane = threadIdx.x & 31;
    const int e = blockIdx.x*8 + warp;
    if (e >= NEDGE) return;
    const int s = src_idx[(size_t)r*NEDGE + e];
    const int d = dst_idx[(size_t)r*NEDGE + e];
    const int h = lane >> 3;
    float ex = g_ex[r][(size_t)e*NH + h];
    float ss = g_ssum[r][(size_t)d*NH + h];
    float alpha = ex / (ss + 1e-9f);
    float4 hv = *(const float4*)(g_hs[r] + (size_t)s*HDF + lane*4);
    float* out = g_rst + ((size_t)d*RELS + r)*HDF + lane*4;
    red_v4(out, alpha*hv.x, alpha*hv.y, alpha*hv.z, alpha*hv.w);
}

// =====================================================================
// K5: w = tanh(elu(rst+bias_g)@W1 + b1) . W2, accumulate per-relation mean
// same GEMM skeleton as K1; A transformed (elu+bias) at load time
// =====================================================================
__global__ __launch_bounds__(256, 2)
void k_w_gemm(const float* __restrict__ bias_g, const float* __restrict__ W1,
              const float* __restrict__ b1, const float* __restrict__ W2)
{
    __shared__ float As[16][132];
    __shared__ float Bs[16][132];
    __shared__ float bias_s[RELS*HDF];
    __shared__ float sh3[RELS];
    const int tid = threadIdx.x;
    const int tx = tid & 15, ty = tid >> 4;
    const int rowBase = blockIdx.x * 128;

    for (int i = tid; i < RELS*HDF; i += 256) bias_s[i] = bias_g[i];
    if (tid < RELS) sh3[tid] = 0.f;
    __syncthreads();

    float4 ra[2], rb[2];
    #pragma unroll
    for (int it = 0; it < 2; it++) {
        int f4 = tid + it*256;
        int arow = f4 >> 2, ak4 = f4 & 3;
        int grow = rowBase + arow; if (grow >= NR) grow = NR-1;
        int rr = grow % RELS;
        float4 v = *(const float4*)(g_rst + (size_t)grow*HDF + ak4*4);
        int cb = rr*HDF + ak4*4;
        v.x = elu1(v.x + bias_s[cb+0]); v.y = elu1(v.y + bias_s[cb+1]);
        v.z = elu1(v.z + bias_s[cb+2]); v.w = elu1(v.w + bias_s[cb+3]);
        ra[it] = v;
        int bk = f4 >> 5, bj4 = f4 & 31;
        rb[it] = *(const float4*)(W1 + (size_t)bk*HDF + bj4*4);
    }

    float acc[8][8];
    #pragma unroll
    for (int i = 0; i < 8; i++)
        #pragma unroll
        for (int j = 0; j < 8; j++) acc[i][j] = 0.f;

    #pragma unroll 1
    for (int kc = 0; kc < 8; kc++) {
        if (kc) __syncthreads();
        #pragma unroll
        for (int it = 0; it < 2; it++) {
            int f4 = tid + it*256;
            int arow = f4 >> 2, ak4 = f4 & 3;
            As[ak4*4+0][arow] = ra[it].x;
            As[ak4*4+1][arow] = ra[it].y;
            As[ak4*4+2][arow] = ra[it].z;
            As[ak4*4+3][arow] = ra[it].w;
            int bk = f4 >> 5, bj4 = f4 & 31;
            *(float4*)&Bs[bk][bj4*4] = rb[it];
        }
        __syncthreads();
        if (kc < 7) {
            #pragma unroll
            for (int it = 0; it < 2; it++) {
                int f4 = tid + it*256;
                int arow = f4 >> 2, ak4 = f4 & 3;
                int grow = rowBase + arow; if (grow >= NR) grow = NR-1;
                int rr = grow % RELS;
                int col = (kc+1)*16 + ak4*4;
                float4 v = *(const float4*)(g_rst + (size_t)grow*HDF + col);
                int cb = rr*HDF + col;
                v.x = elu1(v.x + bias_s[cb+0]); v.y = elu1(v.y + bias_s[cb+1]);
                v.z = elu1(v.z + bias_s[cb+2]); v.w = elu1(v.w + bias_s[cb+3]);
                ra[it] = v;
                int bk = f4 >> 5, bj4 = f4 & 31;
                rb[it] = *(const float4*)(W1 + (size_t)((kc+1)*16 + bk)*HDF + bj4*4);
            }
        }
        #pragma unroll
        for (int k = 0; k < 16; k++) {
            float a0[8], b0[8];
            *(float4*)&a0[0] = *(const float4*)&As[k][ty*8];
            *(float4*)&a0[4] = *(const float4*)&As[k][ty*8+4];
            *(float4*)&b0[0] = *(const float4*)&Bs[k][tx*8];
            *(float4*)&b0[4] = *(const float4*)&Bs[k][tx*8+4];
            #pragma unroll
            for (int i = 0; i < 8; i++)
                #pragma unroll
                for (int j = 0; j < 8; j++)
                    acc[i][j] = fmaf(a0[i], b0[j], acc[i][j]);
        }
    }

    // epilogue: tanh + dot W2, reduce rows over 16 tx lanes, per-rel accumulate
    float b1v[8], w2v[8];
    #pragma unroll
    for (int j = 0; j < 8; j++) { b1v[j] = b1[tx*8+j]; w2v[j] = W2[tx*8+j]; }
    float s3[RELS] = {0.f, 0.f, 0.f};
    #pragma unroll
    for (int i = 0; i < 8; i++) {
        int grow = rowBase + ty*8 + i;
        float part = 0.f;
        #pragma unroll
        for (int j = 0; j < 8; j++)
            part = fmaf(fast_tanh(acc[i][j] + b1v[j]), w2v[j], part);
        part += __shfl_xor_sync(0xFFFFFFFFu, part, 1);
        part += __shfl_xor_sync(0xFFFFFFFFu, part, 2);
        part += __shfl_xor_sync(0xFFFFFFFFu, part, 4);
        part += __shfl_xor_sync(0xFFFFFFFFu, part, 8);
        if (tx == 0 && grow < NR)
            s3[grow % RELS] += part;
    }
    if (tx == 0) {
        #pragma unroll
        for (int rr = 0; rr < RELS; rr++)
            if (s3[rr] != 0.f) atomicAdd(&sh3[rr], s3[rr]);
    }
    __syncthreads();
    if (tid < RELS) atomicAdd(&g_wacc[tid], sh3[tid]);
}

// ---------------- K6: softmax over relation means ----------------
__global__ void k_softmax(float* __restrict__ out, int out_size)
{
    if (threadIdx.x == 0) {
        float w[RELS], mx = -3.0e38f;
        #pragma unroll
        for (int r = 0; r < RELS; r++) { w[r] = g_wacc[r] / (float)NODES; mx = fmaxf(mx, w[r]); }
        float sum = 0.f;
        #pragma unroll
        for (int r = 0; r < RELS; r++) { w[r] = __expf(w[r] - mx); sum += w[r]; }
        #pragma unroll
        for (int r = 0; r < RELS; r++) {
            float a = w[r] / sum;
            g_aw[r] = a;
            if (out_size >= NODES*HDF + RELS)
                out[(size_t)NODES*HDF + r] = a;
        }
    }
}

// ---------------- K7: z = sum_r a[r] * elu(rst[n][r] + bias_g[r]) ----------------
__global__ void k_final(const float* __restrict__ bias_g, float* __restrict__ out)
{
    const size_t idx = (size_t)blockIdx.x*256 + threadIdx.x;
    if (idx >= (size_t)NODES*32) return;
    const int n = (int)(idx >> 5);
    const int c4 = ((int)idx & 31) * 4;
    float4 accv = make_float4(0.f,0.f,0.f,0.f);
    #pragma unroll
    for (int r = 0; r < RELS; r++) {
        float a = g_aw[r];
        float4 v = *(const float4*)(g_rst + ((size_t)n*RELS + r)*HDF + c4);
        float4 b = *(const float4*)(bias_g + (size_t)r*HDF + c4);
        accv.x = fmaf(a, elu1(v.x + b.x), accv.x);
        accv.y = fmaf(a, elu1(v.y + b.y), accv.y);
        accv.z = fmaf(a, elu1(v.z + b.z), accv.z);
        accv.w = fmaf(a, elu1(v.w + b.w), accv.w);
    }
    *(float4*)(out + (size_t)n*HDF + c4) = accv;
}

// ---------------- launch ----------------
extern "C" void kernel_launch(void* const* d_in, const int* in_sizes, int n_in,
                              void* d_out, int out_size)
{
    const float* dst_feat  = (const float*)d_in[0];
    const float* src_feats = (const float*)d_in[1];
    const int*   src_idx   = (const int*)  d_in[2];
    const int*   dst_idx   = (const int*)  d_in[3];
    const float* Wt_dst    = (const float*)d_in[4];
    const float* bt_dst    = (const float*)d_in[5];
    const float* Wt_src    = (const float*)d_in[6];
    const float* bt_src    = (const float*)d_in[7];
    const float* Wg        = (const float*)d_in[8];
    const float* attn_l    = (const float*)d_in[9];
    const float* attn_r    = (const float*)d_in[10];
    const float* bias_g    = (const float*)d_in[11];
    const float* W1        = (const float*)d_in[12];
    const float* b1        = (const float*)d_in[13];
    const float* W2        = (const float*)d_in[14];
    float* out = (float*)d_out;

    k_prep1<<<dim3(8, RELS), 256>>>(Wt_src, bt_src, Wg, attn_r);
    k_prep2<<<RELS, 256>>>(Wt_dst, bt_dst);
    k_init<<<37500, 256>>>();
    k_hs_gemm<<<dim3((NODES + 127)/128, RELS), 256>>>(src_feats, attn_l);
    k_er<<<(NODES + 7)/8, 256>>>(dst_feat);
    k_edge_a<<<dim3((NEDGE + 255)/256, RELS), 256>>>(src_idx, dst_idx);
    for (int r = 0; r < RELS; r++)
        k_edge_b<<<(NEDGE + 7)/8, 256>>>(src_idx, dst_idx, r);
    k_w_gemm<<<(NR + 127)/128, 256>>>(bias_g, W1, b1, W2);
    k_softmax<<<1, 32>>>(out, out_size);
    k_final<<<(NODES*32 + 255)/256, 256>>>(bias_g, out);
}